// round 2
// baseline (speedup 1.0000x reference)
#include <cuda_runtime.h>

// Problem constants (fixed by the dataset shapes)
#define P_ 2
#define B_ 96
#define A_ 32
#define N_ (B_ * A_)      // 3072
#define MD_ 4
#define MA_ 4
#define NPOLB_ 8
#define C_LK_ 0.0897935610625833f
#define THREADS_ 256

__global__ __launch_bounds__(THREADS_) void lkball_kernel(
    const float* __restrict__ coords,        // (P,N,3)
    const int*   __restrict__ block_type,    // (P,B)
    const int*   __restrict__ min_sep,       // (P,B,B)
    const int*   __restrict__ all_bonds,     // (NT,A,2)
    const int*   __restrict__ bond_ranges,   // (NT,A,2)
    const int*   __restrict__ n_donH,        // (NT)
    const int*   __restrict__ n_acc,         // (NT)
    const int*   __restrict__ donH_inds,     // (NT,MD)
    const int*   __restrict__ don_hvy_inds,  // (NT,MD)
    const int*   __restrict__ acc_inds,      // (NT,MA)
    const int*   __restrict__ hyb,           // (NT,MA)
    const int*   __restrict__ is_h,          // (NT,A)
    const float* __restrict__ lk_params,     // (NT,A,4)
    const int*   __restrict__ path_dist,     // (NT,A,A)
    const float* __restrict__ lkb_glob,      // (3): cutoff, ramp2, d2_low
    const float* __restrict__ wgen_glob,     // (2): wdist, wang
    const float* __restrict__ sp2_tors,      // (2)
    const float* __restrict__ sp3_tors,      // (2)
    const float* __restrict__ ring_tors,     // (2)
    float*       __restrict__ out)           // (2,P)
{
    const int tid = threadIdx.x;
    const int bid = blockIdx.x;        // [0, P*B)
    const int p = bid / B_;
    const int b = bid % B_;
    const int t = block_type[p * B_ + b];

    __shared__ float s_px[NPOLB_], s_py[NPOLB_], s_pz[NPOLB_];
    __shared__ float s_ri[NPOLB_], s_invlam[NPOLB_], s_coef[NPOLB_];
    __shared__ float s_w0[NPOLB_][3], s_w1[NPOLB_][3];
    __shared__ int   s_valid[NPOLB_], s_ai[NPOLB_];
    __shared__ int   s_pd[NPOLB_][A_];
    __shared__ int   s_msep[B_];
    __shared__ int   s_bt[B_];
    __shared__ float s_glob[3];   // cutoff^2, 1/ramp2, d2_low+ramp2

    const float* cblk = coords + (size_t)(p * N_ + b * A_) * 3;

    // ---- phase 1: per-slot polar atom + water geometry (threads 0..7) ----
    if (tid < NPOLB_) {
        const int k = tid;
        const float wdist = wgen_glob[0];
        int valid, ai;
        float px, py, pz;
        float w0x, w0y, w0z, w1x, w1y, w1z;
        if (k < MD_) {
            // donor slot k
            valid = (k < n_donH[t]) ? 1 : 0;
            const int hv = don_hvy_inds[t * MD_ + k];
            const int hh = donH_inds[t * MD_ + k];
            ai = hv;
            px = cblk[3 * hv + 0]; py = cblk[3 * hv + 1]; pz = cblk[3 * hv + 2];
            float dx = cblk[3 * hh + 0] - px;
            float dy = cblk[3 * hh + 1] - py;
            float dz = cblk[3 * hh + 2] - pz;
            const float inv = rsqrtf(dx * dx + dy * dy + dz * dz + 1e-12f);
            w0x = px + wdist * dx * inv;
            w0y = py + wdist * dy * inv;
            w0z = pz + wdist * dz * inv;
            // second water slot is masked for donors -> park it far away
            w1x = 1.0e4f; w1y = 1.0e4f; w1z = 1.0e4f;
        } else {
            // acceptor slot m
            const int m = k - MD_;
            valid = (m < n_acc[t]) ? 1 : 0;
            const int c = acc_inds[t * MA_ + m];
            ai = c;
            const int r0c = bond_ranges[(t * A_ + c) * 2 + 0];
            const int bs  = all_bonds[(t * A_ + r0c) * 2 + 1];
            const int r0b = bond_ranges[(t * A_ + bs) * 2 + 0];
            const int b2  = all_bonds[(t * A_ + r0b) * 2 + 1];
            px = cblk[3 * c + 0]; py = cblk[3 * c + 1]; pz = cblk[3 * c + 2];
            const float bx = cblk[3 * bs + 0], by = cblk[3 * bs + 1], bz = cblk[3 * bs + 2];
            const float ax = cblk[3 * b2 + 0], ay = cblk[3 * b2 + 1], az = cblk[3 * b2 + 2];
            float e1x = px - bx, e1y = py - by, e1z = pz - bz;
            float inv = rsqrtf(e1x * e1x + e1y * e1y + e1z * e1z + 1e-12f);
            e1x *= inv; e1y *= inv; e1z *= inv;
            const float mx = bx - ax, my = by - ay, mz = bz - az;
            float nx = my * e1z - mz * e1y;
            float ny = mz * e1x - mx * e1z;
            float nz = mx * e1y - my * e1x;
            inv = rsqrtf(nx * nx + ny * ny + nz * nz + 1e-12f);
            nx *= inv; ny *= inv; nz *= inv;
            const float e2x = ny * e1z - nz * e1y;
            const float e2y = nz * e1x - nx * e1z;
            const float e2z = nx * e1y - ny * e1x;
            const float wang = wgen_glob[1];
            const float ct = cosf(wang), st = sinf(wang);
            const int h = hyb[t * MA_ + m];
            const float* tors = (h == 0) ? sp2_tors : ((h == 1) ? sp3_tors : ring_tors);
            const float chi0 = tors[0], chi1 = tors[1];
            const float c0 = cosf(chi0), sn0 = sinf(chi0);
            const float c1 = cosf(chi1), sn1 = sinf(chi1);
            const float a1 = -wdist * ct;
            const float a2 = wdist * st;
            w0x = px + a1 * e1x + a2 * (c0 * e2x + sn0 * nx);
            w0y = py + a1 * e1y + a2 * (c0 * e2y + sn0 * ny);
            w0z = pz + a1 * e1z + a2 * (c0 * e2z + sn0 * nz);
            w1x = px + a1 * e1x + a2 * (c1 * e2x + sn1 * nx);
            w1y = py + a1 * e1y + a2 * (c1 * e2y + sn1 * ny);
            w1z = pz + a1 * e1z + a2 * (c1 * e2z + sn1 * nz);
        }
        const float* pp = lk_params + (size_t)(t * A_ + ai) * 4;
        const float ri = pp[0], dgi = pp[1], lami = pp[2];
        s_px[k] = px; s_py[k] = py; s_pz[k] = pz;
        s_ri[k] = ri;
        s_invlam[k] = 1.0f / lami;
        s_coef[k] = C_LK_ * dgi / lami;
        s_valid[k] = valid;
        s_ai[k] = ai;
        s_w0[k][0] = w0x; s_w0[k][1] = w0y; s_w0[k][2] = w0z;
        s_w1[k][0] = w1x; s_w1[k][1] = w1y; s_w1[k][2] = w1z;
    }
    if (tid >= 32 && tid < 32 + B_) {
        const int i = tid - 32;
        s_bt[i]   = block_type[p * B_ + i];
        s_msep[i] = min_sep[(p * B_ + b) * B_ + i];
    }
    if (tid == 128) {
        const float cutoff = lkb_glob[0];
        const float ramp2  = lkb_glob[1];
        const float d2low  = lkb_glob[2];
        s_glob[0] = cutoff * cutoff;
        s_glob[1] = 1.0f / ramp2;
        s_glob[2] = d2low + ramp2;
    }
    __syncthreads();

    // ---- phase 2: intra-block path-distance rows for the 8 polar atoms ----
    {
        const int k = tid >> 5, aj = tid & 31;  // 256 threads == 8*32
        s_pd[k][aj] = path_dist[(t * A_ + s_ai[k]) * A_ + aj];
    }
    __syncthreads();

    const float cut2      = s_glob[0];
    const float inv_ramp2 = s_glob[1];
    const float thresh    = s_glob[2];

    // ---- phase 3: pair loop over all atoms j of pose p ----
    float acc0 = 0.0f, acc1 = 0.0f;
    const float* cpose = coords + (size_t)p * N_ * 3;
    for (int j = tid; j < N_; j += THREADS_) {
        const int bj = j >> 5;
        const int aj = j & 31;
        const int tj = s_bt[bj];
        if (is_h[tj * A_ + aj]) continue;            // only heavy j contribute
        const float cx = cpose[3 * j + 0];
        const float cy = cpose[3 * j + 1];
        const float cz = cpose[3 * j + 2];
        const float* pj = lk_params + (size_t)(tj * A_ + aj) * 4;
        const float rj   = pj[0];
        const float volj = pj[3];
        const bool same = (bj == b);
        const int isep = s_msep[bj];
#pragma unroll
        for (int k = 0; k < NPOLB_; k++) {
            if (!s_valid[k]) continue;
            const int sep = same ? s_pd[k][aj] : isep;
            if (sep < 4) continue;
            const float dx = s_px[k] - cx;
            const float dy = s_py[k] - cy;
            const float dz = s_pz[k] - cz;
            const float d2 = fmaxf(dx * dx + dy * dy + dz * dz, 0.01f);
            if (d2 >= cut2) continue;                // ~95% of pairs exit here
            const float d = sqrtf(d2);
            const float x = (d - s_ri[k] - rj) * s_invlam[k];
            const float lk = s_coef[k] * volj * __expf(-x * x) / d2;
            // nearest attached water
            const float u0 = s_w0[k][0] - cx, u1 = s_w0[k][1] - cy, u2 = s_w0[k][2] - cz;
            const float v0 = s_w1[k][0] - cx, v1 = s_w1[k][1] - cy, v2 = s_w1[k][2] - cz;
            const float d2w0 = u0 * u0 + u1 * u1 + u2 * u2;
            const float d2w1 = v0 * v0 + v1 * v1 + v2 * v2;
            const float d2wmin = fminf(d2w0, d2w1);
            const float wt = fminf(fmaxf((thresh - d2wmin) * inv_ramp2, 0.0f), 1.0f);
            const float frac = wt * wt * (3.0f - 2.0f * wt);
            acc0 += lk;
            acc1 += lk * frac;
        }
    }

    // ---- reduction: warp shuffle -> smem -> 2 atomics per CTA ----
    const int lane = tid & 31;
    const int wid = tid >> 5;
#pragma unroll
    for (int o = 16; o > 0; o >>= 1) {
        acc0 += __shfl_down_sync(0xFFFFFFFFu, acc0, o);
        acc1 += __shfl_down_sync(0xFFFFFFFFu, acc1, o);
    }
    __shared__ float r0[THREADS_ / 32], r1[THREADS_ / 32];
    if (lane == 0) { r0[wid] = acc0; r1[wid] = acc1; }
    __syncthreads();
    if (tid == 0) {
        float t0 = 0.0f, t1 = 0.0f;
#pragma unroll
        for (int w = 0; w < THREADS_ / 32; w++) { t0 += r0[w]; t1 += r1[w]; }
        atomicAdd(&out[p], t0);          // out[0, p]
        atomicAdd(&out[P_ + p], t1);     // out[1, p]
    }
}

extern "C" void kernel_launch(void* const* d_in, const int* in_sizes, int n_in,
                              void* d_out, int out_size) {
    const float* coords       = (const float*)d_in[0];
    const int*   block_type   = (const int*)  d_in[1];
    const int*   min_sep      = (const int*)  d_in[2];
    // d_in[3] = bt_n_atoms (unused by the reference)
    const int*   all_bonds    = (const int*)  d_in[4];
    const int*   bond_ranges  = (const int*)  d_in[5];
    const int*   n_donH       = (const int*)  d_in[6];
    const int*   n_acc        = (const int*)  d_in[7];
    const int*   donH_inds    = (const int*)  d_in[8];
    const int*   don_hvy_inds = (const int*)  d_in[9];
    const int*   acc_inds     = (const int*)  d_in[10];
    const int*   hyb          = (const int*)  d_in[11];
    const int*   is_h         = (const int*)  d_in[12];
    const float* lk_params    = (const float*)d_in[13];
    const int*   path_dist    = (const int*)  d_in[14];
    const float* lkb_glob     = (const float*)d_in[15];
    const float* wgen_glob    = (const float*)d_in[16];
    const float* sp2_tors     = (const float*)d_in[17];
    const float* sp3_tors     = (const float*)d_in[18];
    const float* ring_tors    = (const float*)d_in[19];
    float* out = (float*)d_out;

    cudaMemsetAsync(out, 0, (size_t)out_size * sizeof(float), 0);
    lkball_kernel<<<P_ * B_, THREADS_>>>(
        coords, block_type, min_sep, all_bonds, bond_ranges,
        n_donH, n_acc, donH_inds, don_hvy_inds, acc_inds, hyb, is_h,
        lk_params, path_dist, lkb_glob, wgen_glob,
        sp2_tors, sp3_tors, ring_tors, out);
}

// round 3
// speedup vs baseline: 1.6397x; 1.6397x over previous
#include <cuda_runtime.h>

// Problem constants (fixed by the dataset shapes)
#define P_ 2
#define B_ 96
#define A_ 32
#define N_ (B_ * A_)      // 3072
#define MD_ 4
#define MA_ 4
#define NPOLB_ 8
#define NSLOT_ (P_ * B_ * NPOLB_)   // 1536
#define C_LK_ 0.0897935610625833f
#define PAIR_THREADS_ 128

// Scratch (device globals — no allocation allowed)
__device__ float4 g_posr[P_ * N_];        // (x,y,z,rj) per atom
__device__ float  g_vol[P_ * N_];         // volj, 0 for hydrogens
__device__ float4 g_slot[NSLOT_ * 4];     // per-slot record, 4x float4

// ---------------------------------------------------------------------------
// Setup: CTAs 0..23 pack j-atom data (6144 atoms); CTAs 24..29 build the
// 1536 polar-slot records (water geometry + LK coefficients).
// ---------------------------------------------------------------------------
__global__ __launch_bounds__(256) void setup_kernel(
    const float* __restrict__ coords,        // (P,N,3)
    const int*   __restrict__ block_type,    // (P,B)
    const int*   __restrict__ all_bonds,     // (NT,A,2)
    const int*   __restrict__ bond_ranges,   // (NT,A,2)
    const int*   __restrict__ n_donH,        // (NT)
    const int*   __restrict__ n_acc,         // (NT)
    const int*   __restrict__ donH_inds,     // (NT,MD)
    const int*   __restrict__ don_hvy_inds,  // (NT,MD)
    const int*   __restrict__ acc_inds,      // (NT,MA)
    const int*   __restrict__ hyb,           // (NT,MA)
    const int*   __restrict__ is_h,          // (NT,A)
    const float* __restrict__ lk_params,     // (NT,A,4)
    const float* __restrict__ wgen_glob,     // (2): wdist, wang
    const float* __restrict__ sp2_tors,
    const float* __restrict__ sp3_tors,
    const float* __restrict__ ring_tors)
{
    const int tid = threadIdx.x;
    const int bid = blockIdx.x;

    if (bid < (P_ * N_) / 256) {
        // ---- pack j-atom stream ----
        const int idx = bid * 256 + tid;          // [0, P*N)
        const int p  = idx / N_;
        const int jj = idx - p * N_;
        const int bj = jj >> 5;
        const int aj = jj & 31;
        const int tj = block_type[p * B_ + bj];
        const float x = coords[3 * idx + 0];
        const float y = coords[3 * idx + 1];
        const float z = coords[3 * idx + 2];
        const float rj   = lk_params[(tj * A_ + aj) * 4 + 0];
        const float volj = lk_params[(tj * A_ + aj) * 4 + 3];
        const bool heavy = (is_h[tj * A_ + aj] == 0);
        g_posr[idx] = make_float4(x, y, z, rj);
        g_vol[idx]  = heavy ? volj : 0.0f;
        return;
    }

    // ---- slot records ----
    const int s = (bid - (P_ * N_) / 256) * 256 + tid;   // [0, 1536)
    if (s >= NSLOT_) return;
    const int p = s / (B_ * NPOLB_);
    const int r = s - p * (B_ * NPOLB_);
    const int b = r >> 3;
    const int k = r & 7;
    const int t = block_type[p * B_ + b];
    const float* cblk = coords + (size_t)(p * N_ + b * A_) * 3;
    const float wdist = wgen_glob[0];

    int valid, ai;
    float px, py, pz;
    float w0x, w0y, w0z, w1x, w1y, w1z;
    if (k < MD_) {
        valid = (k < n_donH[t]) ? 1 : 0;
        const int hv = don_hvy_inds[t * MD_ + k];
        const int hh = donH_inds[t * MD_ + k];
        ai = hv;
        px = cblk[3 * hv + 0]; py = cblk[3 * hv + 1]; pz = cblk[3 * hv + 2];
        float dx = cblk[3 * hh + 0] - px;
        float dy = cblk[3 * hh + 1] - py;
        float dz = cblk[3 * hh + 2] - pz;
        const float inv = rsqrtf(dx * dx + dy * dy + dz * dz + 1e-12f);
        w0x = px + wdist * dx * inv;
        w0y = py + wdist * dy * inv;
        w0z = pz + wdist * dz * inv;
        w1x = 1.0e4f; w1y = 1.0e4f; w1z = 1.0e4f;   // masked 2nd water
    } else {
        const int m = k - MD_;
        valid = (m < n_acc[t]) ? 1 : 0;
        const int c = acc_inds[t * MA_ + m];
        ai = c;
        const int r0c = bond_ranges[(t * A_ + c) * 2 + 0];
        const int bs  = all_bonds[(t * A_ + r0c) * 2 + 1];
        const int r0b = bond_ranges[(t * A_ + bs) * 2 + 0];
        const int b2  = all_bonds[(t * A_ + r0b) * 2 + 1];
        px = cblk[3 * c + 0]; py = cblk[3 * c + 1]; pz = cblk[3 * c + 2];
        const float bx = cblk[3 * bs + 0], by = cblk[3 * bs + 1], bz = cblk[3 * bs + 2];
        const float ax = cblk[3 * b2 + 0], ay = cblk[3 * b2 + 1], az = cblk[3 * b2 + 2];
        float e1x = px - bx, e1y = py - by, e1z = pz - bz;
        float inv = rsqrtf(e1x * e1x + e1y * e1y + e1z * e1z + 1e-12f);
        e1x *= inv; e1y *= inv; e1z *= inv;
        const float mx = bx - ax, my = by - ay, mz = bz - az;
        float nx = my * e1z - mz * e1y;
        float ny = mz * e1x - mx * e1z;
        float nz = mx * e1y - my * e1x;
        inv = rsqrtf(nx * nx + ny * ny + nz * nz + 1e-12f);
        nx *= inv; ny *= inv; nz *= inv;
        const float e2x = ny * e1z - nz * e1y;
        const float e2y = nz * e1x - nx * e1z;
        const float e2z = nx * e1y - ny * e1x;
        const float wang = wgen_glob[1];
        const float ct = cosf(wang), st = sinf(wang);
        const int h = hyb[t * MA_ + m];
        const float* tors = (h == 0) ? sp2_tors : ((h == 1) ? sp3_tors : ring_tors);
        const float c0 = cosf(tors[0]), sn0 = sinf(tors[0]);
        const float c1 = cosf(tors[1]), sn1 = sinf(tors[1]);
        const float a1 = -wdist * ct;
        const float a2 = wdist * st;
        w0x = px + a1 * e1x + a2 * (c0 * e2x + sn0 * nx);
        w0y = py + a1 * e1y + a2 * (c0 * e2y + sn0 * ny);
        w0z = pz + a1 * e1z + a2 * (c0 * e2z + sn0 * nz);
        w1x = px + a1 * e1x + a2 * (c1 * e2x + sn1 * nx);
        w1y = py + a1 * e1y + a2 * (c1 * e2y + sn1 * ny);
        w1z = pz + a1 * e1z + a2 * (c1 * e2z + sn1 * nz);
    }
    const float* pp = lk_params + (size_t)(t * A_ + ai) * 4;
    const float ri = pp[0], dgi = pp[1], lami = pp[2];
    g_slot[s * 4 + 0] = make_float4(px, py, pz, ri);
    g_slot[s * 4 + 1] = make_float4(w0x, w0y, w0z, 1.0f / lami);
    g_slot[s * 4 + 2] = make_float4(w1x, w1y, w1z, C_LK_ * dgi / lami);
    g_slot[s * 4 + 3] = make_float4(__int_as_float(valid), __int_as_float(t),
                                    __int_as_float(ai), 0.0f);
}

// ---------------------------------------------------------------------------
// Pair kernel: one CTA per polar slot (1536 CTAs x 128 threads).
// Slot data in registers; j-stream is coherent float4 reads (L1-resident).
// ---------------------------------------------------------------------------
__global__ __launch_bounds__(PAIR_THREADS_) void pair_kernel(
    const int*   __restrict__ min_sep,       // (P,B,B)
    const int*   __restrict__ path_dist,     // (NT,A,A)
    const float* __restrict__ lkb_glob,      // cutoff, ramp2, d2_low
    float*       __restrict__ out)           // (2,P)
{
    const int sid = blockIdx.x;              // [0, 1536)
    const int p = sid / (B_ * NPOLB_);
    const int rb = sid - p * (B_ * NPOLB_);
    const int b = rb >> 3;

    const float4 f3 = g_slot[sid * 4 + 3];
    const int valid = __float_as_int(f3.x);
    if (!valid) return;                      // uniform across CTA, before syncs
    const int t  = __float_as_int(f3.y);
    const int ai = __float_as_int(f3.z);

    const float4 f0 = g_slot[sid * 4 + 0];
    const float4 f1 = g_slot[sid * 4 + 1];
    const float4 f2 = g_slot[sid * 4 + 2];
    const float px = f0.x, py = f0.y, pz = f0.z, ri = f0.w;
    const float w0x = f1.x, w0y = f1.y, w0z = f1.z, invlam = f1.w;
    const float w1x = f2.x, w1y = f2.y, w1z = f2.z, coef = f2.w;

    const float cutoff = lkb_glob[0];
    const float ramp2  = lkb_glob[1];
    const float cut2   = cutoff * cutoff;
    const float inv_ramp2 = 1.0f / ramp2;
    const float thresh = lkb_glob[2] + ramp2;

    __shared__ int s_pd[A_];
    __shared__ int s_msep[B_];
    const int tid = threadIdx.x;
    if (tid < B_) s_msep[tid] = min_sep[(p * B_ + b) * B_ + tid];
    if (tid >= B_ && tid < B_ + A_)
        s_pd[tid - B_] = path_dist[(t * A_ + ai) * A_ + (tid - B_)];
    __syncthreads();

    const float4* __restrict__ posr = g_posr + p * N_;
    const float*  __restrict__ vol  = g_vol + p * N_;

    float acc0 = 0.0f, acc1 = 0.0f;
#pragma unroll 4
    for (int it = 0; it < N_ / PAIR_THREADS_; it++) {
        const int j = tid + it * PAIR_THREADS_;
        const float4 pr = posr[j];
        const float v = vol[j];
        const float dx = px - pr.x;
        const float dy = py - pr.y;
        const float dz = pz - pr.z;
        const float d2 = fmaxf(dx * dx + dy * dy + dz * dz, 0.01f);
        if (d2 < cut2 && v > 0.0f) {
            const int bj = j >> 5;
            const int sep = (bj == b) ? s_pd[j & 31] : s_msep[bj];
            if (sep >= 4) {
                const float d = sqrtf(d2);
                const float x = (d - ri - pr.w) * invlam;
                const float lk = __fdividef(coef * v * __expf(-x * x), d2);
                const float u0 = w0x - pr.x, u1 = w0y - pr.y, u2 = w0z - pr.z;
                const float q0 = w1x - pr.x, q1 = w1y - pr.y, q2 = w1z - pr.z;
                const float d2w0 = u0 * u0 + u1 * u1 + u2 * u2;
                const float d2w1 = q0 * q0 + q1 * q1 + q2 * q2;
                const float d2wmin = fminf(d2w0, d2w1);
                const float wt = __saturatef((thresh - d2wmin) * inv_ramp2);
                const float frac = wt * wt * (3.0f - 2.0f * wt);
                acc0 += lk;
                acc1 += lk * frac;
            }
        }
    }

    // warp reduce -> smem -> 2 atomics per CTA
    const int lane = tid & 31;
    const int wid = tid >> 5;
#pragma unroll
    for (int o = 16; o > 0; o >>= 1) {
        acc0 += __shfl_down_sync(0xFFFFFFFFu, acc0, o);
        acc1 += __shfl_down_sync(0xFFFFFFFFu, acc1, o);
    }
    __shared__ float r0[PAIR_THREADS_ / 32], r1[PAIR_THREADS_ / 32];
    if (lane == 0) { r0[wid] = acc0; r1[wid] = acc1; }
    __syncthreads();
    if (tid == 0) {
        float t0 = 0.0f, t1 = 0.0f;
#pragma unroll
        for (int w = 0; w < PAIR_THREADS_ / 32; w++) { t0 += r0[w]; t1 += r1[w]; }
        atomicAdd(&out[p], t0);          // out[0, p]
        atomicAdd(&out[P_ + p], t1);     // out[1, p]
    }
}

extern "C" void kernel_launch(void* const* d_in, const int* in_sizes, int n_in,
                              void* d_out, int out_size) {
    const float* coords       = (const float*)d_in[0];
    const int*   block_type   = (const int*)  d_in[1];
    const int*   min_sep      = (const int*)  d_in[2];
    // d_in[3] = bt_n_atoms (unused)
    const int*   all_bonds    = (const int*)  d_in[4];
    const int*   bond_ranges  = (const int*)  d_in[5];
    const int*   n_donH       = (const int*)  d_in[6];
    const int*   n_acc        = (const int*)  d_in[7];
    const int*   donH_inds    = (const int*)  d_in[8];
    const int*   don_hvy_inds = (const int*)  d_in[9];
    const int*   acc_inds     = (const int*)  d_in[10];
    const int*   hyb          = (const int*)  d_in[11];
    const int*   is_h         = (const int*)  d_in[12];
    const float* lk_params    = (const float*)d_in[13];
    const int*   path_dist    = (const int*)  d_in[14];
    const float* lkb_glob     = (const float*)d_in[15];
    const float* wgen_glob    = (const float*)d_in[16];
    const float* sp2_tors     = (const float*)d_in[17];
    const float* sp3_tors     = (const float*)d_in[18];
    const float* ring_tors    = (const float*)d_in[19];
    float* out = (float*)d_out;

    cudaMemsetAsync(out, 0, (size_t)out_size * sizeof(float), 0);

    const int setup_blocks = (P_ * N_) / 256 + (NSLOT_ + 255) / 256;  // 24 + 6
    setup_kernel<<<setup_blocks, 256>>>(
        coords, block_type, all_bonds, bond_ranges, n_donH, n_acc,
        donH_inds, don_hvy_inds, acc_inds, hyb, is_h, lk_params,
        wgen_glob, sp2_tors, sp3_tors, ring_tors);

    pair_kernel<<<NSLOT_, PAIR_THREADS_>>>(min_sep, path_dist, lkb_glob, out);
}